// round 15
// baseline (speedup 1.0000x reference)
#include <cuda_runtime.h>
#include <cuda_fp16.h>
#include <math.h>

#define N_ATOMS 10000
#define N_PAIRS 320000
#define CC 64

typedef unsigned long long ull;

// ---------------- f32x2 helpers (Blackwell packed fp32) ----------------
__device__ __forceinline__ ull pack2(float x) {
    ull r; asm("mov.b64 %0, {%1, %1};" : "=l"(r) : "f"(x)); return r;
}
__device__ __forceinline__ ull pack_pair(float lo, float hi) {
    ull r; asm("mov.b64 %0, {%1, %2};" : "=l"(r) : "f"(lo), "f"(hi)); return r;
}
__device__ __forceinline__ void fma2(ull& acc, ull a, ull b) {
    asm("fma.rn.f32x2 %0, %1, %2, %0;" : "+l"(acc) : "l"(a), "l"(b));
}
__device__ __forceinline__ float2 unpack2(ull v) {
    float2 f; asm("mov.b64 {%0, %1}, %2;" : "=f"(f.x), "=f"(f.y) : "l"(v)); return f;
}
__device__ __forceinline__ float tanh_fast(float x) {
    float y; asm("tanh.approx.f32 %0, %1;" : "=f"(y) : "f"(x)); return y;
}

// ---------------- scratch (device globals; no allocation allowed) ----------------
__device__ float g_p1in[N_ATOMS * 64];
__device__ float g_v[N_ATOMS * 3];
__device__ float g_p1scat[N_ATOMS * 128];
__device__ float g_p3acc[N_ATOMS * 192];
__device__ float g_piWn[2 * 10 * 64 * 64];       // [z][b][k][c]
__device__ float g_A[N_ATOMS * 640];             // p1in @ Wtop + pib   [atom][b][c] f32
__device__ unsigned int g_Bh[N_ATOMS * 320];     // p1in @ Wbot  [atom][b][c/2] half2
__device__ int   g_cnt[N_ATOMS];
__device__ int   g_woff[N_ATOMS];
__device__ int   g_perm[N_PAIRS];

// ---------------- side stream for fork-join overlap ----------------
struct SideStream {
    cudaStream_t s = nullptr;
    cudaEvent_t fork = nullptr, join = nullptr;
    SideStream() {
        if (cudaStreamCreateWithFlags(&s, cudaStreamNonBlocking) != cudaSuccess) { s = nullptr; return; }
        if (cudaEventCreateWithFlags(&fork, cudaEventDisableTiming) != cudaSuccess) { s = nullptr; return; }
        if (cudaEventCreateWithFlags(&join, cudaEventDisableTiming) != cudaSuccess) { s = nullptr; return; }
    }
};
static SideStream g_ss;

// ---------------- kernel 0: zero scratch ----------------
__global__ void zero_kernel() {
    int idx = blockIdx.x * blockDim.x + threadIdx.x;
    if (idx < N_ATOMS * 3)   g_v[idx] = 0.0f;
    if (idx < N_ATOMS * 128) g_p1scat[idx] = 0.0f;
    if (idx < N_ATOMS * 192) g_p3acc[idx] = 0.0f;
    if (idx < N_ATOMS)       g_cnt[idx] = 0;
}

// ---------------- kernel A: fused count + v accumulation ----------------
__global__ void count_vacc_kernel(const int* __restrict__ ind2,
                                  const float* __restrict__ d3,
                                  const float* __restrict__ fc) {
    int p = blockIdx.x * blockDim.x + threadIdx.x;
    if (p >= N_PAIRS) return;
    int i = ind2[2 * p];
    atomicAdd(&g_cnt[i], 1);
    float f = fc[p];
    atomicAdd(&g_v[i * 3 + 0], d3[p * 3 + 0] * f);
    atomicAdd(&g_v[i * 3 + 1], d3[p * 3 + 1] * f);
    atomicAdd(&g_v[i * 3 + 2], d3[p * 3 + 2] * f);
}

// ---------------- kernel B: exclusive scan (1 block, 1024 thr) ----------------
__global__ void scan_kernel() {
    __shared__ int warp_sums[32];
    __shared__ int carry;
    int tid = threadIdx.x;
    int lane = tid & 31, wid = tid >> 5;
    if (tid == 0) carry = 0;
    __syncthreads();
    for (int base = 0; base < N_ATOMS; base += 1024) {
        int idx = base + tid;
        int v = (idx < N_ATOMS) ? g_cnt[idx] : 0;
        int x = v;
        #pragma unroll
        for (int off = 1; off < 32; off <<= 1) {
            int t = __shfl_up_sync(0xffffffffu, x, off);
            if (lane >= off) x += t;
        }
        if (lane == 31) warp_sums[wid] = x;
        __syncthreads();
        if (wid == 0) {
            int s = warp_sums[lane];
            #pragma unroll
            for (int off = 1; off < 32; off <<= 1) {
                int t = __shfl_up_sync(0xffffffffu, s, off);
                if (lane >= off) s += t;
            }
            warp_sums[lane] = s;
        }
        __syncthreads();
        int excl = carry + (wid > 0 ? warp_sums[wid - 1] : 0) + (x - v);
        if (idx < N_ATOMS) g_woff[idx] = excl;
        __syncthreads();
        if (tid == 0) carry += warp_sums[31];
        __syncthreads();
    }
}

__global__ void scatter_kernel(const int* __restrict__ ind2) {
    int p = blockIdx.x * blockDim.x + threadIdx.x;
    if (p >= N_PAIRS) return;
    int pos = atomicAdd(&g_woff[ind2[2 * p]], 1);
    g_perm[pos] = p;
}

// ---------------- kernel 0b: reorder piW into [z][b][k][c] ----------------
__global__ void prep_kernel(const float* __restrict__ piW) {
    int idx = blockIdx.x * blockDim.x + threadIdx.x;
    if (idx >= 2 * 10 * 64 * 64) return;
    int c  = idx & 63;
    int k  = (idx >> 6) & 63;
    int zb = idx >> 12;
    int z  = zb / 10, b = zb % 10;
    g_piWn[idx] = piW[(z * 64 + k) * 640 + c * 10 + b];
}

// ---------------- kernel 1: p1_in = tanh(tanh(p1@W1+b1)@W2+b2) ----------------
__global__ void p1in_kernel(const float* __restrict__ p1,
                            const float* __restrict__ W1, const float* __restrict__ b1,
                            const float* __restrict__ W2, const float* __restrict__ b2) {
    __shared__ float W1s[4096], W2s[4096], b1s[64], b2s[64];
    __shared__ float xr[4 * 64], hs[4 * 64];
    int tid = threadIdx.x;
    for (int idx = tid; idx < 4096; idx += 256) { W1s[idx] = W1[idx]; W2s[idx] = W2[idx]; }
    if (tid < 64) { b1s[tid] = b1[tid]; b2s[tid] = b2[tid]; }
    int slot = tid >> 6, c = tid & 63;
    int a = blockIdx.x * 4 + slot;
    xr[slot * 64 + c] = p1[a * 64 + c];
    __syncthreads();
    float h = b1s[c];
    #pragma unroll 8
    for (int k = 0; k < 64; ++k) h += xr[slot * 64 + k] * W1s[k * 64 + c];
    hs[slot * 64 + c] = tanhf(h);
    __syncthreads();
    float o = b2s[c];
    #pragma unroll 8
    for (int k = 0; k < 64; ++k) o += hs[slot * 64 + k] * W2s[k * 64 + c];
    g_p1in[a * 64 + c] = tanhf(o);
}

// ---------------- kernel 1b: A/B builder — f32x2 GEMM, 16 atoms/warp ----------------
#define AB_SMEM_FLOATS 12544
__global__ __launch_bounds__(256) void ab_kernel(const float* __restrict__ pib) {
    extern __shared__ float absm[];
    float* xs = absm;            // [k][atom] stride 132
    float* Wb = absm + 8448;
    int tid = threadIdx.x;
    int zb = blockIdx.y, z = zb / 10, b = zb % 10;
    int abase = blockIdx.x * 128;

    for (int idx = tid; idx < 4096; idx += 256) Wb[idx] = g_piWn[zb * 4096 + idx];
    {
        int k = tid & 63, a0 = tid >> 6;
        #pragma unroll 8
        for (int r = 0; r < 32; ++r) {
            int a = a0 + r * 4;
            int ga = abase + a;
            xs[k * 132 + a] = (ga < N_ATOMS) ? g_p1in[ga * 64 + k] : 0.0f;
        }
    }
    __syncthreads();

    int lane = tid & 31, wg = tid >> 5;
    int c2 = 2 * lane;
    ull bias = 0ULL;
    if (z == 0) bias = pack_pair(pib[c2 * 10 + b], pib[(c2 + 1) * 10 + b]);
    ull acc[16];
    #pragma unroll
    for (int r = 0; r < 16; ++r) acc[r] = bias;

    const ull* WbU = (const ull*)Wb;
    const float* xw = xs + wg * 16;
    #pragma unroll 2
    for (int k = 0; k < 64; ++k) {
        float4 x0 = *(const float4*)(xw + k * 132);
        float4 x1 = *(const float4*)(xw + k * 132 + 4);
        float4 x2 = *(const float4*)(xw + k * 132 + 8);
        float4 x3 = *(const float4*)(xw + k * 132 + 12);
        ull w = WbU[k * 32 + lane];
        fma2(acc[0],  pack2(x0.x), w);
        fma2(acc[1],  pack2(x0.y), w);
        fma2(acc[2],  pack2(x0.z), w);
        fma2(acc[3],  pack2(x0.w), w);
        fma2(acc[4],  pack2(x1.x), w);
        fma2(acc[5],  pack2(x1.y), w);
        fma2(acc[6],  pack2(x1.z), w);
        fma2(acc[7],  pack2(x1.w), w);
        fma2(acc[8],  pack2(x2.x), w);
        fma2(acc[9],  pack2(x2.y), w);
        fma2(acc[10], pack2(x2.z), w);
        fma2(acc[11], pack2(x2.w), w);
        fma2(acc[12], pack2(x3.x), w);
        fma2(acc[13], pack2(x3.y), w);
        fma2(acc[14], pack2(x3.z), w);
        fma2(acc[15], pack2(x3.w), w);
    }

    #pragma unroll
    for (int r = 0; r < 16; ++r) {
        int a = abase + wg * 16 + r;
        if (a < N_ATOMS) {
            float2 v = unpack2(acc[r]);
            if (z == 0) {
                *(float2*)(g_A + (size_t)a * 640 + b * 64 + c2) = v;
            } else {
                __half2 h = __float22half2_rn(v);
                g_Bh[(size_t)a * 320 + b * 32 + lane] = *(unsigned int*)&h;
            }
        }
    }
}

// ---------------- kernel 3: main per-pair kernel (sorted pairs) ----------------
#define PAIR_SMEM_FLOATS 21952
__global__ __launch_bounds__(256, 2) void pair_kernel(
                            const int* __restrict__ ind2,
                            const float* __restrict__ p3,
                            const float* __restrict__ basis,
                            const float* __restrict__ d3,
                            const float* __restrict__ fc,
                            const float* __restrict__ iiW) {
    extern __shared__ float sm[];
    float* Z     = sm;
    float* sIp   = sm + 8256;
    float* Ws    = sm + 12416;
    float* contrib = sm + 8256;      // aliases sIp+Ws after stage 2
    float* sB    = sm + 20608;
    float* sD3   = sm + 21248;
    float* sFc   = sm + 21440;
    int*   sI    = (int*)(sm + 21504);
    int*   sJ    = sI + 64;
    float* sGeo  = sm + 21632;
    int*   sPm   = (int*)(sm + 21888);

    int tid = threadIdx.x;
    int lane = tid & 31;
    int wg   = tid >> 5;
    int pbase = blockIdx.x * 64;

    if (tid < 64) {
        int pm = g_perm[pbase + tid];
        sPm[tid] = pm;
        sI[tid]  = ind2[2 * pm];
        sJ[tid]  = ind2[2 * pm + 1];
        sFc[tid] = fc[pm];
    }
    __syncthreads();
    for (int idx = tid; idx < 640; idx += 256) {
        int m = idx / 10, b = idx - 10 * m;
        sB[idx] = basis[(size_t)sPm[m] * 10 + b];
    }
    for (int idx = tid; idx < 192; idx += 256) {
        int m = idx / 3, r = idx - 3 * m;
        sD3[idx] = d3[(size_t)sPm[m] * 3 + r];
    }
    for (int idx = tid; idx < 8192; idx += 256) Ws[idx] = iiW[idx];
    __syncthreads();

    // ---- stage 1: i_pair[m][c] = sum_b tanh(A[i]+B[j]) * basis
    // lane = (row-half rh, quad q): 4 channels per lane, 2 rows per iter, 4 iters.
    {
        int rh = lane >> 4;          // 0/1
        int q  = lane & 15;          // channel quad (4 ch)
        #pragma unroll
        for (int it = 0; it < 4; ++it) {
            int m = wg * 8 + it * 2 + rh;
            const float4* Ai = (const float4*)(g_A + (size_t)sI[m] * 640) + q;
            const uint2*  Bj = (const uint2*)(g_Bh + (size_t)sJ[m] * 320) + q;
            float4 a4[10]; uint2 bh[10];
            #pragma unroll
            for (int b = 0; b < 10; ++b) { a4[b] = Ai[b * 16]; bh[b] = Bj[b * 16]; }  // b-block = 64 ch = 16 float4 = 16 uint2
            float s0 = 0.0f, s1 = 0.0f, s2 = 0.0f, s3 = 0.0f;
            #pragma unroll
            for (int b = 0; b < 10; ++b) {
                float2 b0 = __half22float2(*(__half2*)&bh[b].x);
                float2 b1 = __half22float2(*(__half2*)&bh[b].y);
                float bas = sB[m * 10 + b];
                s0 += tanh_fast(a4[b].x + b0.x) * bas;
                s1 += tanh_fast(a4[b].y + b0.y) * bas;
                s2 += tanh_fast(a4[b].z + b1.x) * bas;
                s3 += tanh_fast(a4[b].w + b1.y) * bas;
            }
            int c0 = q * 4;
            sIp[m * 65 + c0]     = s0;
            sIp[m * 65 + c0 + 1] = s1;
            sIp[m * 65 + c0 + 2] = s2;
            sIp[m * 65 + c0 + 3] = s3;
        }
    }
    __syncthreads();

    // ---- stage 2: z = tanh(i_pair @ iiW)  (64 -> 128), into Z (stride 129) ----
    {
        int n0 = wg * 16;
        ull z0[8], z1[8];
        #pragma unroll
        for (int t = 0; t < 8; ++t) { z0[t] = 0ULL; z1[t] = 0ULL; }
        const float* ir0 = sIp + lane * 65;
        const float* ir1 = sIp + (lane + 32) * 65;
        #pragma unroll 4
        for (int k = 0; k < 64; ++k) {
            ull A0 = pack2(ir0[k]);
            ull A1 = pack2(ir1[k]);
            const ull* qp = (const ull*)(Ws + k * 128 + n0);
            #pragma unroll
            for (int t = 0; t < 8; ++t) {
                ull w = qp[t];
                fma2(z0[t], A0, w);
                fma2(z1[t], A1, w);
            }
        }
        float* zr0 = Z + lane * 129;
        float* zr1 = Z + (lane + 32) * 129;
        #pragma unroll
        for (int t = 0; t < 8; ++t) {
            float2 a = unpack2(z0[t]);
            float2 b = unpack2(z1[t]);
            zr0[n0 + 2 * t]     = tanh_fast(a.x);
            zr0[n0 + 2 * t + 1] = tanh_fast(a.y);
            zr1[n0 + 2 * t]     = tanh_fast(b.x);
            zr1[n0 + 2 * t + 1] = tanh_fast(b.y);
        }
    }
    __syncthreads();     // stage-2 reads of sIp/Ws done; contrib may now overwrite

    // ---- stage 3a: per-pair geometry ----
    if (tid < 64) {
        int m = tid;
        int i = sI[m];
        float fcv = sFc[m];
        float dx = sD3[m * 3 + 0], dy = sD3[m * 3 + 1], dz = sD3[m * 3 + 2];
        float vx = g_v[i * 3 + 0], vy = g_v[i * 3 + 1], vz = g_v[i * 3 + 2];
        float proj = vx * dx + vy * dy + vz * dz;
        float wx = vx - proj * dx, wy = vy - proj * dy, wzc = vz - proj * dz;
        float w2 = wx * wx + wy * wy + wzc * wzc;
        float gdeg = w2 / (w2 + 1e-4f);
        float rs = rsqrtf(w2 + 1e-6f);
        float sc = rs * gdeg;
        sGeo[m * 4 + 0] = wx * sc;
        sGeo[m * 4 + 1] = wy * sc;
        sGeo[m * 4 + 2] = wzc * sc;
        sGeo[m * 4 + 3] = gdeg * fcv * fcv;
    }
    __syncthreads();

    // ---- stage 3b: per-pair p3 contribution into smem (4 threads/pair) ----
    {
        int m = tid >> 2, q = tid & 3;
        int j = sJ[m];
        float dx = sD3[m * 3 + 0], dy = sD3[m * 3 + 1], dz = sD3[m * 3 + 2];
        float t3x = sGeo[m * 4 + 0], t3y = sGeo[m * 4 + 1], t3z = sGeo[m * 4 + 2];
        float tb  = sGeo[m * 4 + 3];
        const float* zr = Z + m * 129;
        const float* p3j = p3 + (size_t)j * 192;
        float* cw = contrib + m * 193;
        #pragma unroll
        for (int t4 = 0; t4 < 4; ++t4) {
            int c0 = q * 16 + 4 * t4;
            float g0 = zr[64 + c0], g1 = zr[64 + c0 + 1], g2 = zr[64 + c0 + 2], g3 = zr[64 + c0 + 3];
            float k0 = g0 * tb, k1 = g1 * tb, k2 = g2 * tb, k3 = g3 * tb;
            float4 px = *(const float4*)(p3j + c0);
            float4 py = *(const float4*)(p3j + 64 + c0);
            float4 pz = *(const float4*)(p3j + 128 + c0);
            cw[c0]           = px.x * g0 + dx * g0 + t3x * k0;
            cw[c0 + 1]       = px.y * g1 + dx * g1 + t3x * k1;
            cw[c0 + 2]       = px.z * g2 + dx * g2 + t3x * k2;
            cw[c0 + 3]       = px.w * g3 + dx * g3 + t3x * k3;
            cw[64 + c0]      = py.x * g0 + dy * g0 + t3y * k0;
            cw[64 + c0 + 1]  = py.y * g1 + dy * g1 + t3y * k1;
            cw[64 + c0 + 2]  = py.z * g2 + dy * g2 + t3y * k2;
            cw[64 + c0 + 3]  = py.w * g3 + dy * g3 + t3y * k3;
            cw[128 + c0]     = pz.x * g0 + dz * g0 + t3z * k0;
            cw[128 + c0 + 1] = pz.y * g1 + dz * g1 + t3z * k1;
            cw[128 + c0 + 2] = pz.z * g2 + dz * g2 + t3z * k2;
            cw[128 + c0 + 3] = pz.w * g3 + dz * g3 + t3z * k3;
        }
    }
    __syncthreads();

    // ---- stage 3c: segmented reduction over sorted pairs, one RED per run ----
    {
        bool isP1 = (tid < 128);
        int ch = isP1 ? tid : (tid - 128);
        const float* src = isP1 ? (Z + ch) : (contrib + ch);
        int sstride = isP1 ? 129 : 193;
        float* dst = isP1 ? (g_p1scat + ch) : (g_p3acc + ch);
        int dstride = isP1 ? 128 : 192;
        float acc = 0.0f;
        #pragma unroll 8
        for (int m = 0; m < 64; ++m) {
            acc += src[m * sstride];
            if (m == 63 || sI[m + 1] != sI[m]) {
                atomicAdd(dst + (size_t)sI[m] * dstride, acc);
                acc = 0.0f;
            }
        }
    }
    if (tid < 64) {
        int ch = 128 + tid;
        float acc = 0.0f;
        #pragma unroll 8
        for (int m = 0; m < 64; ++m) {
            acc += contrib[m * 193 + ch];
            if (m == 63 || sI[m + 1] != sI[m]) {
                atomicAdd(g_p3acc + (size_t)sI[m] * 192 + ch, acc);
                acc = 0.0f;
            }
        }
    }
}

// ---------------- kernel 4: atom-side tail, writes d_out ----------------
#define FINAL_SMEM_FLOATS 36032
__global__ void atom_final_kernel(const float* __restrict__ postW1,
                                  const float* __restrict__ postW2,
                                  const float* __restrict__ eqW,
                                  const float* __restrict__ q1W,
                                  const float* __restrict__ q1b,
                                  const float* __restrict__ q2W,
                                  const float* __restrict__ q2b,
                                  float* __restrict__ out) {
    extern __shared__ float sm[];
    float* W1s  = sm;
    float* W2s  = sm + 8192;
    float* Es   = sm + 12288;
    float* Q1s  = sm + 16384;
    float* Q2s  = sm + 24576;
    float* b1s  = sm + 32768;
    float* b2s  = sm + 32832;
    float* ps   = sm + 32960;
    float* p3a  = sm + 33472;
    float* sH   = sm + 34240;
    float* sP1  = sm + 34496;
    float* sP3n = sm + 34752;
    float* sD   = sm + 35520;
    float* sH2  = sm + 35776;

    int tid = threadIdx.x;
    for (int idx = tid; idx < 8192; idx += 256) W1s[idx] = postW1[idx];
    for (int idx = tid; idx < 4096; idx += 256) { W2s[idx] = postW2[idx]; Es[idx] = eqW[idx]; }
    for (int idx = tid; idx < 8192; idx += 256) { Q1s[idx] = q1W[idx]; Q2s[idx] = q2W[idx]; }
    if (tid < 64)  b1s[tid] = q1b[tid];
    if (tid < 128) b2s[tid] = q2b[tid];

    int slot = tid >> 6, c = tid & 63;
    int abase = blockIdx.x * 68;
    for (int it = 0; it < 17; ++it) {
        __syncthreads();
        int a = abase + it * 4 + slot;
        bool valid = (a < N_ATOMS);
        if (valid) {
            ps[slot * 128 + c]       = g_p1scat[a * 128 + c];
            ps[slot * 128 + 64 + c]  = g_p1scat[a * 128 + 64 + c];
            p3a[slot * 192 + c]       = g_p3acc[a * 192 + c];
            p3a[slot * 192 + 64 + c]  = g_p3acc[a * 192 + 64 + c];
            p3a[slot * 192 + 128 + c] = g_p3acc[a * 192 + 128 + c];
        } else {
            ps[slot * 128 + c] = 0.0f; ps[slot * 128 + 64 + c] = 0.0f;
            p3a[slot * 192 + c] = 0.0f; p3a[slot * 192 + 64 + c] = 0.0f;
            p3a[slot * 192 + 128 + c] = 0.0f;
        }
        __syncthreads();
        float h = 0.0f;
        #pragma unroll 8
        for (int k = 0; k < 128; ++k) h += ps[slot * 128 + k] * W1s[k * 64 + c];
        sH[slot * 64 + c] = tanhf(h);
        __syncthreads();
        float o = 0.0f;
        float p0 = 0.0f, p1v = 0.0f, p2 = 0.0f;
        #pragma unroll 8
        for (int k = 0; k < 64; ++k) {
            o += sH[slot * 64 + k] * W2s[k * 64 + c];
            float e = Es[k * 64 + c];
            p0  += p3a[slot * 192 + k]       * e;
            p1v += p3a[slot * 192 + 64 + k]  * e;
            p2  += p3a[slot * 192 + 128 + k] * e;
        }
        sP1[slot * 64 + c] = tanhf(o);
        sP3n[slot * 192 + c]       = p0;
        sP3n[slot * 192 + 64 + c]  = p1v;
        sP3n[slot * 192 + 128 + c] = p2;
        sD[slot * 64 + c] = p0 * p0 + p1v * p1v + p2 * p2;
        __syncthreads();
        float h2 = b1s[c];
        #pragma unroll 8
        for (int k = 0; k < 64; ++k) {
            h2 += sP1[slot * 64 + k] * Q1s[k * 64 + c];
            h2 += sD[slot * 64 + k]  * Q1s[(64 + k) * 64 + c];
        }
        sH2[slot * 64 + c] = tanhf(h2);
        __syncthreads();
        float o1 = b2s[c], o2 = b2s[64 + c];
        #pragma unroll 8
        for (int k = 0; k < 64; ++k) {
            float hh = sH2[slot * 64 + k];
            o1 += hh * Q2s[k * 128 + c];
            o2 += hh * Q2s[k * 128 + 64 + c];
        }
        o1 = tanhf(o1);
        o2 = tanhf(o2);
        if (valid) {
            out[a * 64 + c] = o1;
            float* po = out + N_ATOMS * 64 + (size_t)a * 192;
            po[c]        = sP3n[slot * 192 + c]       * o2;
            po[64 + c]   = sP3n[slot * 192 + 64 + c]  * o2;
            po[128 + c]  = sP3n[slot * 192 + 128 + c] * o2;
        }
    }
}

// ---------------- launch ----------------
extern "C" void kernel_launch(void* const* d_in, const int* in_sizes, int n_in,
                              void* d_out, int out_size) {
    const int*   ind2   = (const int*)d_in[0];
    const float* p1     = (const float*)d_in[1];
    const float* p3     = (const float*)d_in[2];
    const float* basis  = (const float*)d_in[3];
    const float* d3     = (const float*)d_in[4];
    const float* fc     = (const float*)d_in[5];
    const float* preW1  = (const float*)d_in[6];
    const float* preb1  = (const float*)d_in[7];
    const float* preW2  = (const float*)d_in[8];
    const float* preb2  = (const float*)d_in[9];
    const float* piW    = (const float*)d_in[10];
    const float* pib    = (const float*)d_in[11];
    const float* iiW    = (const float*)d_in[12];
    const float* postW1 = (const float*)d_in[13];
    const float* postW2 = (const float*)d_in[14];
    const float* eqW    = (const float*)d_in[15];
    const float* q1W    = (const float*)d_in[16];
    const float* q1b    = (const float*)d_in[17];
    const float* q2W    = (const float*)d_in[18];
    const float* q2b    = (const float*)d_in[19];
    float* out = (float*)d_out;

    cudaFuncSetAttribute(ab_kernel, cudaFuncAttributeMaxDynamicSharedMemorySize,
                         AB_SMEM_FLOATS * 4);
    cudaFuncSetAttribute(pair_kernel, cudaFuncAttributeMaxDynamicSharedMemorySize,
                         PAIR_SMEM_FLOATS * 4);
    cudaFuncSetAttribute(atom_final_kernel, cudaFuncAttributeMaxDynamicSharedMemorySize,
                         FINAL_SMEM_FLOATS * 4);

    dim3 ab_grid((N_ATOMS + 127) / 128, 20, 1);

    if (g_ss.s) {
        cudaEventRecord(g_ss.fork, 0);
        cudaStreamWaitEvent(g_ss.s, g_ss.fork, 0);

        prep_kernel<<<(2 * 10 * 64 * 64 + 255) / 256, 256>>>(piW);
        p1in_kernel<<<N_ATOMS / 4, 256>>>(p1, preW1, preb1, preW2, preb2);
        zero_kernel<<<(N_ATOMS * 192 + 255) / 256, 256, 0, g_ss.s>>>();
        ab_kernel<<<ab_grid, 256, AB_SMEM_FLOATS * 4>>>(pib);
        count_vacc_kernel<<<(N_PAIRS + 255) / 256, 256, 0, g_ss.s>>>(ind2, d3, fc);
        scan_kernel<<<1, 1024, 0, g_ss.s>>>();
        scatter_kernel<<<(N_PAIRS + 255) / 256, 256, 0, g_ss.s>>>(ind2);

        cudaEventRecord(g_ss.join, g_ss.s);
        cudaStreamWaitEvent(0, g_ss.join, 0);
    } else {
        prep_kernel<<<(2 * 10 * 64 * 64 + 255) / 256, 256>>>(piW);
        p1in_kernel<<<N_ATOMS / 4, 256>>>(p1, preW1, preb1, preW2, preb2);
        zero_kernel<<<(N_ATOMS * 192 + 255) / 256, 256>>>();
        ab_kernel<<<ab_grid, 256, AB_SMEM_FLOATS * 4>>>(pib);
        count_vacc_kernel<<<(N_PAIRS + 255) / 256, 256>>>(ind2, d3, fc);
        scan_kernel<<<1, 1024>>>();
        scatter_kernel<<<(N_PAIRS + 255) / 256, 256>>>(ind2);
    }

    pair_kernel<<<N_PAIRS / 64, 256, PAIR_SMEM_FLOATS * 4>>>(ind2, p3, basis, d3, fc, iiW);
    atom_final_kernel<<<148, 256, FINAL_SMEM_FLOATS * 4>>>(postW1, postW2, eqW,
                                                           q1W, q1b, q2W, q2b, out);
}

// round 16
// speedup vs baseline: 1.0607x; 1.0607x over previous
#include <cuda_runtime.h>
#include <math.h>

#define N_ATOMS 10000
#define N_PAIRS 320000
#define CC 64

typedef unsigned long long ull;

// ---------------- f32x2 helpers (Blackwell packed fp32) ----------------
__device__ __forceinline__ ull pack2(float x) {
    ull r; asm("mov.b64 %0, {%1, %1};" : "=l"(r) : "f"(x)); return r;
}
__device__ __forceinline__ ull pack_pair(float lo, float hi) {
    ull r; asm("mov.b64 %0, {%1, %2};" : "=l"(r) : "f"(lo), "f"(hi)); return r;
}
__device__ __forceinline__ void fma2(ull& acc, ull a, ull b) {
    asm("fma.rn.f32x2 %0, %1, %2, %0;" : "+l"(acc) : "l"(a), "l"(b));
}
__device__ __forceinline__ float2 unpack2(ull v) {
    float2 f; asm("mov.b64 {%0, %1}, %2;" : "=f"(f.x), "=f"(f.y) : "l"(v)); return f;
}
__device__ __forceinline__ float tanh_fast(float x) {
    float y; asm("tanh.approx.f32 %0, %1;" : "=f"(y) : "f"(x)); return y;
}

// ---------------- scratch (device globals; no allocation allowed) ----------------
__device__ float g_p1in[N_ATOMS * 64];
__device__ float g_v[N_ATOMS * 3];
__device__ float g_p1scat[N_ATOMS * 128];
__device__ float g_p3acc[N_ATOMS * 192];
__device__ float g_piWn[2 * 10 * 64 * 64];       // [z][b][k][c]
__device__ float g_A[N_ATOMS * 640];             // p1in @ Wtop + pib   [atom][b][c] f32
__device__ float g_B[N_ATOMS * 640];             // p1in @ Wbot         [atom][b][c] f32
__device__ int   g_cnt[N_ATOMS];
__device__ int   g_woff[N_ATOMS];
__device__ int   g_perm[N_PAIRS];

// ---------------- side stream for fork-join overlap ----------------
struct SideStream {
    cudaStream_t s = nullptr;
    cudaEvent_t fork = nullptr, join = nullptr;
    SideStream() {
        if (cudaStreamCreateWithFlags(&s, cudaStreamNonBlocking) != cudaSuccess) { s = nullptr; return; }
        if (cudaEventCreateWithFlags(&fork, cudaEventDisableTiming) != cudaSuccess) { s = nullptr; return; }
        if (cudaEventCreateWithFlags(&join, cudaEventDisableTiming) != cudaSuccess) { s = nullptr; return; }
    }
};
static SideStream g_ss;

// ---------------- kernel 0: zero scratch ----------------
__global__ void zero_kernel() {
    int idx = blockIdx.x * blockDim.x + threadIdx.x;
    if (idx < N_ATOMS * 3)   g_v[idx] = 0.0f;
    if (idx < N_ATOMS * 128) g_p1scat[idx] = 0.0f;
    if (idx < N_ATOMS * 192) g_p3acc[idx] = 0.0f;
    if (idx < N_ATOMS)       g_cnt[idx] = 0;
}

// ---------------- kernel A: fused count + v accumulation ----------------
__global__ void count_vacc_kernel(const int* __restrict__ ind2,
                                  const float* __restrict__ d3,
                                  const float* __restrict__ fc) {
    int p = blockIdx.x * blockDim.x + threadIdx.x;
    if (p >= N_PAIRS) return;
    int i = ind2[2 * p];
    atomicAdd(&g_cnt[i], 1);
    float f = fc[p];
    atomicAdd(&g_v[i * 3 + 0], d3[p * 3 + 0] * f);
    atomicAdd(&g_v[i * 3 + 1], d3[p * 3 + 1] * f);
    atomicAdd(&g_v[i * 3 + 2], d3[p * 3 + 2] * f);
}

// ---------------- kernel B: exclusive scan (1 block, 1024 thr) ----------------
__global__ void scan_kernel() {
    __shared__ int warp_sums[32];
    __shared__ int carry;
    int tid = threadIdx.x;
    int lane = tid & 31, wid = tid >> 5;
    if (tid == 0) carry = 0;
    __syncthreads();
    for (int base = 0; base < N_ATOMS; base += 1024) {
        int idx = base + tid;
        int v = (idx < N_ATOMS) ? g_cnt[idx] : 0;
        int x = v;
        #pragma unroll
        for (int off = 1; off < 32; off <<= 1) {
            int t = __shfl_up_sync(0xffffffffu, x, off);
            if (lane >= off) x += t;
        }
        if (lane == 31) warp_sums[wid] = x;
        __syncthreads();
        if (wid == 0) {
            int s = warp_sums[lane];
            #pragma unroll
            for (int off = 1; off < 32; off <<= 1) {
                int t = __shfl_up_sync(0xffffffffu, s, off);
                if (lane >= off) s += t;
            }
            warp_sums[lane] = s;
        }
        __syncthreads();
        int excl = carry + (wid > 0 ? warp_sums[wid - 1] : 0) + (x - v);
        if (idx < N_ATOMS) g_woff[idx] = excl;
        __syncthreads();
        if (tid == 0) carry += warp_sums[31];
        __syncthreads();
    }
}

__global__ void scatter_kernel(const int* __restrict__ ind2) {
    int p = blockIdx.x * blockDim.x + threadIdx.x;
    if (p >= N_PAIRS) return;
    int pos = atomicAdd(&g_woff[ind2[2 * p]], 1);
    g_perm[pos] = p;
}

// ---------------- kernel 0b: reorder piW into [z][b][k][c] ----------------
__global__ void prep_kernel(const float* __restrict__ piW) {
    int idx = blockIdx.x * blockDim.x + threadIdx.x;
    if (idx >= 2 * 10 * 64 * 64) return;
    int c  = idx & 63;
    int k  = (idx >> 6) & 63;
    int zb = idx >> 12;
    int z  = zb / 10, b = zb % 10;
    g_piWn[idx] = piW[(z * 64 + k) * 640 + c * 10 + b];
}

// ---------------- kernel 1: p1_in = tanh(tanh(p1@W1+b1)@W2+b2) ----------------
__global__ void p1in_kernel(const float* __restrict__ p1,
                            const float* __restrict__ W1, const float* __restrict__ b1,
                            const float* __restrict__ W2, const float* __restrict__ b2) {
    __shared__ float W1s[4096], W2s[4096], b1s[64], b2s[64];
    __shared__ float xr[4 * 64], hs[4 * 64];
    int tid = threadIdx.x;
    for (int idx = tid; idx < 4096; idx += 256) { W1s[idx] = W1[idx]; W2s[idx] = W2[idx]; }
    if (tid < 64) { b1s[tid] = b1[tid]; b2s[tid] = b2[tid]; }
    int slot = tid >> 6, c = tid & 63;
    int a = blockIdx.x * 4 + slot;
    xr[slot * 64 + c] = p1[a * 64 + c];
    __syncthreads();
    float h = b1s[c];
    #pragma unroll 8
    for (int k = 0; k < 64; ++k) h += xr[slot * 64 + k] * W1s[k * 64 + c];
    hs[slot * 64 + c] = tanhf(h);
    __syncthreads();
    float o = b2s[c];
    #pragma unroll 8
    for (int k = 0; k < 64; ++k) o += hs[slot * 64 + k] * W2s[k * 64 + c];
    g_p1in[a * 64 + c] = tanhf(o);
}

// ---------------- kernel 1b: A/B builder — f32x2 GEMM, 16 atoms/warp ----------------
#define AB_SMEM_FLOATS 12544
__global__ __launch_bounds__(256) void ab_kernel(const float* __restrict__ pib) {
    extern __shared__ float absm[];
    float* xs = absm;            // [k][atom] stride 132
    float* Wb = absm + 8448;
    int tid = threadIdx.x;
    int zb = blockIdx.y, z = zb / 10, b = zb % 10;
    int abase = blockIdx.x * 128;

    for (int idx = tid; idx < 4096; idx += 256) Wb[idx] = g_piWn[zb * 4096 + idx];
    {
        int k = tid & 63, a0 = tid >> 6;
        #pragma unroll 8
        for (int r = 0; r < 32; ++r) {
            int a = a0 + r * 4;
            int ga = abase + a;
            xs[k * 132 + a] = (ga < N_ATOMS) ? g_p1in[ga * 64 + k] : 0.0f;
        }
    }
    __syncthreads();

    int lane = tid & 31, wg = tid >> 5;
    int c2 = 2 * lane;
    ull bias = 0ULL;
    if (z == 0) bias = pack_pair(pib[c2 * 10 + b], pib[(c2 + 1) * 10 + b]);
    ull acc[16];
    #pragma unroll
    for (int r = 0; r < 16; ++r) acc[r] = bias;

    const ull* WbU = (const ull*)Wb;
    const float* xw = xs + wg * 16;
    #pragma unroll 2
    for (int k = 0; k < 64; ++k) {
        float4 x0 = *(const float4*)(xw + k * 132);
        float4 x1 = *(const float4*)(xw + k * 132 + 4);
        float4 x2 = *(const float4*)(xw + k * 132 + 8);
        float4 x3 = *(const float4*)(xw + k * 132 + 12);
        ull w = WbU[k * 32 + lane];
        fma2(acc[0],  pack2(x0.x), w);
        fma2(acc[1],  pack2(x0.y), w);
        fma2(acc[2],  pack2(x0.z), w);
        fma2(acc[3],  pack2(x0.w), w);
        fma2(acc[4],  pack2(x1.x), w);
        fma2(acc[5],  pack2(x1.y), w);
        fma2(acc[6],  pack2(x1.z), w);
        fma2(acc[7],  pack2(x1.w), w);
        fma2(acc[8],  pack2(x2.x), w);
        fma2(acc[9],  pack2(x2.y), w);
        fma2(acc[10], pack2(x2.z), w);
        fma2(acc[11], pack2(x2.w), w);
        fma2(acc[12], pack2(x3.x), w);
        fma2(acc[13], pack2(x3.y), w);
        fma2(acc[14], pack2(x3.z), w);
        fma2(acc[15], pack2(x3.w), w);
    }

    float* out = z ? g_B : g_A;
    #pragma unroll
    for (int r = 0; r < 16; ++r) {
        int a = abase + wg * 16 + r;
        if (a < N_ATOMS) {
            float2 v = unpack2(acc[r]);
            *(float2*)(out + (size_t)a * 640 + b * 64 + c2) = v;
        }
    }
}

// ---------------- kernel 3: main per-pair kernel (sorted pairs, 3 CTAs/SM) ----------------
// smem (floats):
//   Z    [0,     8256)   64x129 (z vectors; [64:128] = gate)
//   sIp  [8256,  12416)  64x65 i_pair
//   Ws   [12416, 16512)  iiW half-chunk 64x64
//   sB   [16512, 17152)  basis 64x10
//   sD3  [17152, 17344)  sFc [17344, 17408)
//   sI/sJ[17408, 17536)
//   sGeo [17536, 17792)  64x4 (t3x,t3y,t3z,tb)
//   sPm  [17792, 17856)  int x64
#define PAIR_SMEM_FLOATS 17856
__global__ __launch_bounds__(256, 3) void pair_kernel(
                            const int* __restrict__ ind2,
                            const float* __restrict__ p3,
                            const float* __restrict__ basis,
                            const float* __restrict__ d3,
                            const float* __restrict__ fc,
                            const float* __restrict__ iiW) {
    extern __shared__ float sm[];
    float* Z     = sm;
    float* sIp   = sm + 8256;
    float* Ws    = sm + 12416;
    float* sB    = sm + 16512;
    float* sD3   = sm + 17152;
    float* sFc   = sm + 17344;
    int*   sI    = (int*)(sm + 17408);
    int*   sJ    = sI + 64;
    float* sGeo  = sm + 17536;
    int*   sPm   = (int*)(sm + 17792);

    int tid = threadIdx.x;
    int lane = tid & 31;
    int wg   = tid >> 5;
    int pbase = blockIdx.x * 64;

    if (tid < 64) {
        int pm = g_perm[pbase + tid];
        sPm[tid] = pm;
        sI[tid]  = ind2[2 * pm];
        sJ[tid]  = ind2[2 * pm + 1];
        sFc[tid] = fc[pm];
    }
    __syncthreads();
    for (int idx = tid; idx < 640; idx += 256) {
        int m = idx / 10, b = idx - 10 * m;
        sB[idx] = basis[(size_t)sPm[m] * 10 + b];
    }
    for (int idx = tid; idx < 192; idx += 256) {
        int m = idx / 3, r = idx - 3 * m;
        sD3[idx] = d3[(size_t)sPm[m] * 3 + r];
    }
    __syncthreads();

    // ---- stage 1: i_pair[m][c] = sum_b tanh(A[i]+B[j]) * basis
    // lane = (row-half rh, quad q): 4 channels/lane, 2 rows per iter, 4 iters.
    // basis blocks processed in 2 groups of 5 to limit register pressure.
    {
        int rh = lane >> 4;          // 0/1
        int q  = lane & 15;          // channel quad (4 ch)
        #pragma unroll
        for (int it = 0; it < 4; ++it) {
            int m = wg * 8 + it * 2 + rh;
            const float4* Ai = (const float4*)(g_A + (size_t)sI[m] * 640) + q;
            const float4* Bj = (const float4*)(g_B + (size_t)sJ[m] * 640) + q;
            float s0 = 0.0f, s1 = 0.0f, s2 = 0.0f, s3 = 0.0f;
            #pragma unroll
            for (int half = 0; half < 2; ++half) {
                float4 a4[5], b4[5];
                #pragma unroll
                for (int b5 = 0; b5 < 5; ++b5) {
                    int b = half * 5 + b5;
                    a4[b5] = Ai[b * 16];
                    b4[b5] = Bj[b * 16];
                }
                #pragma unroll
                for (int b5 = 0; b5 < 5; ++b5) {
                    float bas = sB[m * 10 + half * 5 + b5];
                    s0 += tanh_fast(a4[b5].x + b4[b5].x) * bas;
                    s1 += tanh_fast(a4[b5].y + b4[b5].y) * bas;
                    s2 += tanh_fast(a4[b5].z + b4[b5].z) * bas;
                    s3 += tanh_fast(a4[b5].w + b4[b5].w) * bas;
                }
            }
            int c0 = q * 4;
            sIp[m * 65 + c0]     = s0;
            sIp[m * 65 + c0 + 1] = s1;
            sIp[m * 65 + c0 + 2] = s2;
            sIp[m * 65 + c0 + 3] = s3;
        }
    }

    // ---- stage 2: z = tanh(i_pair @ iiW) (64->128), iiW in 2 col-chunks of 64 ----
    // warp wg -> 8 output cols (within chunk), rows lane & lane+32.
    #pragma unroll
    for (int cc = 0; cc < 2; ++cc) {
        __syncthreads();     // (cc=0: also covers stage-1 sIp writes)
        for (int idx = tid; idx < 4096; idx += 256) {
            int k = idx >> 6, cl = idx & 63;
            Ws[idx] = iiW[k * 128 + cc * 64 + cl];
        }
        __syncthreads();
        int n0 = wg * 8;
        ull z0[4], z1[4];
        #pragma unroll
        for (int t = 0; t < 4; ++t) { z0[t] = 0ULL; z1[t] = 0ULL; }
        const float* ir0 = sIp + lane * 65;
        const float* ir1 = sIp + (lane + 32) * 65;
        #pragma unroll 4
        for (int k = 0; k < 64; ++k) {
            ull A0 = pack2(ir0[k]);
            ull A1 = pack2(ir1[k]);
            const ull* qp = (const ull*)(Ws + k * 64 + n0);
            #pragma unroll
            for (int t = 0; t < 4; ++t) {
                ull w = qp[t];
                fma2(z0[t], A0, w);
                fma2(z1[t], A1, w);
            }
        }
        float* zr0 = Z + lane * 129 + cc * 64;
        float* zr1 = Z + (lane + 32) * 129 + cc * 64;
        #pragma unroll
        for (int t = 0; t < 4; ++t) {
            float2 a = unpack2(z0[t]);
            float2 b = unpack2(z1[t]);
            zr0[n0 + 2 * t]     = tanh_fast(a.x);
            zr0[n0 + 2 * t + 1] = tanh_fast(a.y);
            zr1[n0 + 2 * t]     = tanh_fast(b.x);
            zr1[n0 + 2 * t + 1] = tanh_fast(b.y);
        }
    }
    __syncthreads();

    // ---- stage 3a: per-pair geometry ----
    if (tid < 64) {
        int m = tid;
        int i = sI[m];
        float fcv = sFc[m];
        float dx = sD3[m * 3 + 0], dy = sD3[m * 3 + 1], dz = sD3[m * 3 + 2];
        float vx = g_v[i * 3 + 0], vy = g_v[i * 3 + 1], vz = g_v[i * 3 + 2];
        float proj = vx * dx + vy * dy + vz * dz;
        float wx = vx - proj * dx, wy = vy - proj * dy, wzc = vz - proj * dz;
        float w2 = wx * wx + wy * wy + wzc * wzc;
        float gdeg = w2 / (w2 + 1e-4f);
        float rs = rsqrtf(w2 + 1e-6f);
        float sc = rs * gdeg;
        sGeo[m * 4 + 0] = wx * sc;
        sGeo[m * 4 + 1] = wy * sc;
        sGeo[m * 4 + 2] = wzc * sc;
        sGeo[m * 4 + 3] = gdeg * fcv * fcv;
    }
    __syncthreads();

    // ---- stage 3: fused segmented reduction, p3 contributions computed on the fly ----
    // pass A: tid<128 -> p1 channel tid; tid>=128 -> p3 channel (tid-128) in [0,128)
    {
        bool isP1 = (tid < 128);
        int ch = isP1 ? tid : (tid - 128);
        int r  = ch >> 6, cl = ch & 63;          // used only for p3 side
        float acc = 0.0f;
        if (isP1) {
            const float* src = Z + ch;
            #pragma unroll 8
            for (int m = 0; m < 64; ++m) {
                acc += src[m * 129];
                if (m == 63 || sI[m + 1] != sI[m]) {
                    atomicAdd(g_p1scat + (size_t)sI[m] * 128 + ch, acc);
                    acc = 0.0f;
                }
            }
        } else {
            #pragma unroll 4
            for (int m = 0; m < 64; ++m) {
                float g = Z[m * 129 + 64 + cl];
                float pj = p3[(size_t)sJ[m] * 192 + r * 64 + cl];
                acc += pj * g + sD3[m * 3 + r] * g + sGeo[m * 4 + r] * (g * sGeo[m * 4 + 3]);
                if (m == 63 || sI[m + 1] != sI[m]) {
                    atomicAdd(g_p3acc + (size_t)sI[m] * 192 + r * 64 + cl, acc);
                    acc = 0.0f;
                }
            }
        }
    }
    // pass B: tid<64 -> p3 channel 128+tid (r=2)
    if (tid < 64) {
        int cl = tid;
        float acc = 0.0f;
        #pragma unroll 4
        for (int m = 0; m < 64; ++m) {
            float g = Z[m * 129 + 64 + cl];
            float pj = p3[(size_t)sJ[m] * 192 + 128 + cl];
            acc += pj * g + sD3[m * 3 + 2] * g + sGeo[m * 4 + 2] * (g * sGeo[m * 4 + 3]);
            if (m == 63 || sI[m + 1] != sI[m]) {
                atomicAdd(g_p3acc + (size_t)sI[m] * 192 + 128 + cl, acc);
                acc = 0.0f;
            }
        }
    }
}

// ---------------- kernel 4: atom-side tail, writes d_out ----------------
#define FINAL_SMEM_FLOATS 36032
__global__ void atom_final_kernel(const float* __restrict__ postW1,
                                  const float* __restrict__ postW2,
                                  const float* __restrict__ eqW,
                                  const float* __restrict__ q1W,
                                  const float* __restrict__ q1b,
                                  const float* __restrict__ q2W,
                                  const float* __restrict__ q2b,
                                  float* __restrict__ out) {
    extern __shared__ float sm[];
    float* W1s  = sm;
    float* W2s  = sm + 8192;
    float* Es   = sm + 12288;
    float* Q1s  = sm + 16384;
    float* Q2s  = sm + 24576;
    float* b1s  = sm + 32768;
    float* b2s  = sm + 32832;
    float* ps   = sm + 32960;
    float* p3a  = sm + 33472;
    float* sH   = sm + 34240;
    float* sP1  = sm + 34496;
    float* sP3n = sm + 34752;
    float* sD   = sm + 35520;
    float* sH2  = sm + 35776;

    int tid = threadIdx.x;
    for (int idx = tid; idx < 8192; idx += 256) W1s[idx] = postW1[idx];
    for (int idx = tid; idx < 4096; idx += 256) { W2s[idx] = postW2[idx]; Es[idx] = eqW[idx]; }
    for (int idx = tid; idx < 8192; idx += 256) { Q1s[idx] = q1W[idx]; Q2s[idx] = q2W[idx]; }
    if (tid < 64)  b1s[tid] = q1b[tid];
    if (tid < 128) b2s[tid] = q2b[tid];

    int slot = tid >> 6, c = tid & 63;
    int abase = blockIdx.x * 68;
    for (int it = 0; it < 17; ++it) {
        __syncthreads();
        int a = abase + it * 4 + slot;
        bool valid = (a < N_ATOMS);
        if (valid) {
            ps[slot * 128 + c]       = g_p1scat[a * 128 + c];
            ps[slot * 128 + 64 + c]  = g_p1scat[a * 128 + 64 + c];
            p3a[slot * 192 + c]       = g_p3acc[a * 192 + c];
            p3a[slot * 192 + 64 + c]  = g_p3acc[a * 192 + 64 + c];
            p3a[slot * 192 + 128 + c] = g_p3acc[a * 192 + 128 + c];
        } else {
            ps[slot * 128 + c] = 0.0f; ps[slot * 128 + 64 + c] = 0.0f;
            p3a[slot * 192 + c] = 0.0f; p3a[slot * 192 + 64 + c] = 0.0f;
            p3a[slot * 192 + 128 + c] = 0.0f;
        }
        __syncthreads();
        float h = 0.0f;
        #pragma unroll 8
        for (int k = 0; k < 128; ++k) h += ps[slot * 128 + k] * W1s[k * 64 + c];
        sH[slot * 64 + c] = tanhf(h);
        __syncthreads();
        float o = 0.0f;
        float p0 = 0.0f, p1v = 0.0f, p2 = 0.0f;
        #pragma unroll 8
        for (int k = 0; k < 64; ++k) {
            o += sH[slot * 64 + k] * W2s[k * 64 + c];
            float e = Es[k * 64 + c];
            p0  += p3a[slot * 192 + k]       * e;
            p1v += p3a[slot * 192 + 64 + k]  * e;
            p2  += p3a[slot * 192 + 128 + k] * e;
        }
        sP1[slot * 64 + c] = tanhf(o);
        sP3n[slot * 192 + c]       = p0;
        sP3n[slot * 192 + 64 + c]  = p1v;
        sP3n[slot * 192 + 128 + c] = p2;
        sD[slot * 64 + c] = p0 * p0 + p1v * p1v + p2 * p2;
        __syncthreads();
        float h2 = b1s[c];
        #pragma unroll 8
        for (int k = 0; k < 64; ++k) {
            h2 += sP1[slot * 64 + k] * Q1s[k * 64 + c];
            h2 += sD[slot * 64 + k]  * Q1s[(64 + k) * 64 + c];
        }
        sH2[slot * 64 + c] = tanhf(h2);
        __syncthreads();
        float o1 = b2s[c], o2 = b2s[64 + c];
        #pragma unroll 8
        for (int k = 0; k < 64; ++k) {
            float hh = sH2[slot * 64 + k];
            o1 += hh * Q2s[k * 128 + c];
            o2 += hh * Q2s[k * 128 + 64 + c];
        }
        o1 = tanhf(o1);
        o2 = tanhf(o2);
        if (valid) {
            out[a * 64 + c] = o1;
            float* po = out + N_ATOMS * 64 + (size_t)a * 192;
            po[c]        = sP3n[slot * 192 + c]       * o2;
            po[64 + c]   = sP3n[slot * 192 + 64 + c]  * o2;
            po[128 + c]  = sP3n[slot * 192 + 128 + c] * o2;
        }
    }
}

// ---------------- launch ----------------
extern "C" void kernel_launch(void* const* d_in, const int* in_sizes, int n_in,
                              void* d_out, int out_size) {
    const int*   ind2   = (const int*)d_in[0];
    const float* p1     = (const float*)d_in[1];
    const float* p3     = (const float*)d_in[2];
    const float* basis  = (const float*)d_in[3];
    const float* d3     = (const float*)d_in[4];
    const float* fc     = (const float*)d_in[5];
    const float* preW1  = (const float*)d_in[6];
    const float* preb1  = (const float*)d_in[7];
    const float* preW2  = (const float*)d_in[8];
    const float* preb2  = (const float*)d_in[9];
    const float* piW    = (const float*)d_in[10];
    const float* pib    = (const float*)d_in[11];
    const float* iiW    = (const float*)d_in[12];
    const float* postW1 = (const float*)d_in[13];
    const float* postW2 = (const float*)d_in[14];
    const float* eqW    = (const float*)d_in[15];
    const float* q1W    = (const float*)d_in[16];
    const float* q1b    = (const float*)d_in[17];
    const float* q2W    = (const float*)d_in[18];
    const float* q2b    = (const float*)d_in[19];
    float* out = (float*)d_out;

    cudaFuncSetAttribute(ab_kernel, cudaFuncAttributeMaxDynamicSharedMemorySize,
                         AB_SMEM_FLOATS * 4);
    cudaFuncSetAttribute(pair_kernel, cudaFuncAttributeMaxDynamicSharedMemorySize,
                         PAIR_SMEM_FLOATS * 4);
    cudaFuncSetAttribute(atom_final_kernel, cudaFuncAttributeMaxDynamicSharedMemorySize,
                         FINAL_SMEM_FLOATS * 4);

    dim3 ab_grid((N_ATOMS + 127) / 128, 20, 1);

    if (g_ss.s) {
        cudaEventRecord(g_ss.fork, 0);
        cudaStreamWaitEvent(g_ss.s, g_ss.fork, 0);

        prep_kernel<<<(2 * 10 * 64 * 64 + 255) / 256, 256>>>(piW);
        p1in_kernel<<<N_ATOMS / 4, 256>>>(p1, preW1, preb1, preW2, preb2);
        zero_kernel<<<(N_ATOMS * 192 + 255) / 256, 256, 0, g_ss.s>>>();
        ab_kernel<<<ab_grid, 256, AB_SMEM_FLOATS * 4>>>(pib);
        count_vacc_kernel<<<(N_PAIRS + 255) / 256, 256, 0, g_ss.s>>>(ind2, d3, fc);
        scan_kernel<<<1, 1024, 0, g_ss.s>>>();
        scatter_kernel<<<(N_PAIRS + 255) / 256, 256, 0, g_ss.s>>>(ind2);

        cudaEventRecord(g_ss.join, g_ss.s);
        cudaStreamWaitEvent(0, g_ss.join, 0);
    } else {
        prep_kernel<<<(2 * 10 * 64 * 64 + 255) / 256, 256>>>(piW);
        p1in_kernel<<<N_ATOMS / 4, 256>>>(p1, preW1, preb1, preW2, preb2);
        zero_kernel<<<(N_ATOMS * 192 + 255) / 256, 256>>>();
        ab_kernel<<<ab_grid, 256, AB_SMEM_FLOATS * 4>>>(pib);
        count_vacc_kernel<<<(N_PAIRS + 255) / 256, 256>>>(ind2, d3, fc);
        scan_kernel<<<1, 1024>>>();
        scatter_kernel<<<(N_PAIRS + 255) / 256, 256>>>(ind2);
    }

    pair_kernel<<<N_PAIRS / 64, 256, PAIR_SMEM_FLOATS * 4>>>(ind2, p3, basis, d3, fc, iiW);
    atom_final_kernel<<<148, 256, FINAL_SMEM_FLOATS * 4>>>(postW1, postW2, eqW,
                                                           q1W, q1b, q2W, q2b, out);
}